// round 13
// baseline (speedup 1.0000x reference)
#include <cuda_runtime.h>
#include <cuda_fp16.h>
#include <cstdint>

#define B_SZ 2048
#define H_SZ 2048
#define P_SZ 8192
#define K_TOTAL 2048

// ---------------------------------------------------------------------------
// Scratch (__device__ globals; no cudaMalloc allowed)
// ---------------------------------------------------------------------------
__device__ __align__(1024) float g_proj[(size_t)B_SZ * 3 * H_SZ];
__device__ __align__(1024) __half g_hid_hi[(size_t)B_SZ * H_SZ];
__device__ __align__(1024) __half g_hid_lo[(size_t)B_SZ * H_SZ];
__device__ __align__(1024) __half g_win[(size_t)3 * H_SZ * H_SZ];
__device__ __align__(1024) __half g_wout[(size_t)H_SZ * H_SZ];
__device__ __align__(1024) __half g_gated_hi[(size_t)B_SZ * H_SZ];
__device__ __align__(1024) __half g_gated_lo[(size_t)B_SZ * H_SZ];

// ---------------------------------------------------------------------------
// Baseline-PTX helpers (legal on plain sm_103 target)
// ---------------------------------------------------------------------------
__device__ __forceinline__ uint32_t smem_u32(const void* p) {
    uint32_t a;
    asm("{ .reg .u64 t; cvta.to.shared.u64 t, %1; cvt.u32.u64 %0, t; }"
        : "=r"(a) : "l"(p));
    return a;
}

__device__ __forceinline__ void cp16(uint32_t dst, const void* src) {
    asm volatile("cp.async.cg.shared.global [%0], [%1], 16;"
                 :: "r"(dst), "l"(src));
}
#define CP_COMMIT() asm volatile("cp.async.commit_group;" ::: "memory")
#define CP_WAIT2()  asm volatile("cp.async.wait_group 2;" ::: "memory")

__device__ __forceinline__ void ldsm_x4(uint32_t* r, uint32_t addr) {
    asm volatile("ldmatrix.sync.aligned.m8n8.x4.shared.b16 {%0,%1,%2,%3}, [%4];"
                 : "=r"(r[0]), "=r"(r[1]), "=r"(r[2]), "=r"(r[3]) : "r"(addr));
}

__device__ __forceinline__ void mma_fp16(float* c, const uint32_t* a,
                                         const uint32_t* b) {
    asm volatile(
        "mma.sync.aligned.m16n8k16.row.col.f32.f16.f16.f32 "
        "{%0,%1,%2,%3}, {%4,%5,%6,%7}, {%8,%9}, {%0,%1,%2,%3};"
        : "+f"(c[0]), "+f"(c[1]), "+f"(c[2]), "+f"(c[3])
        : "r"(a[0]), "r"(a[1]), "r"(a[2]), "r"(a[3]), "r"(b[0]), "r"(b[1]));
}

// ---------------------------------------------------------------------------
// Split-fp16 2-product GEMM (D = Ah*B + Al*B) with OPTIONAL interleaved
// copy-role CTAs. When n4copy > 0, every 4th CTA (blockIdx.x % 4 == 3)
// streams the conv_state copy on the DRAM pipe while GEMM CTAs saturate the
// tensor pipe; the wave scheduler backfills as short copy CTAs retire.
// GEMM: CTA tile 128M x 256N, BK=32, 4-stage cp.async (wait_group 2), one
// __syncthreads per iteration. Stage: Ah@0(8K), Al@8K(8K), B@16K(16K)=32KB.
// Row = 64B, XOR swizzle off(r,c4)=r*64+((c4^((r>>1)&3))<<4). 8 warps.
// ---------------------------------------------------------------------------
#define BKI 32
#define NIT (K_TOTAL / BKI)          // 64
#define STG_BYTES 32768
#define NSTG 4
#define SMEM_TOTAL (NSTG * STG_BYTES)   // 128 KB
#define OFF_AL 8192
#define OFF_B  16384

__global__ __launch_bounds__(256)
void mma_gemm_kernel(const __half* __restrict__ Ah,
                     const __half* __restrict__ Al,
                     const __half* __restrict__ Bm,
                     float* __restrict__ C, int Ntotal, int nTilesN,
                     const float4* __restrict__ csrc,
                     float4* __restrict__ cdst, int n4copy) {
    // ---- role resolution ----
    int gemmIdx;
    if (n4copy > 0) {
        if ((blockIdx.x & 3) == 3) {
            // copy role: grid-stride float4 stream
            int copyIdx = blockIdx.x >> 2;
            int nCopyCTAs = gridDim.x >> 2;
            int i = copyIdx * 256 + threadIdx.x;
            int stride = nCopyCTAs * 256;
            for (; i < n4copy; i += stride) cdst[i] = csrc[i];
            return;
        }
        gemmIdx = blockIdx.x - (blockIdx.x >> 2);
    } else {
        gemmIdx = blockIdx.x;
    }
    const int mBase = (gemmIdx / nTilesN) * 128;
    const int nBase = (gemmIdx % nTilesN) * 256;

    extern __shared__ __align__(1024) char smem[];
    const uint32_t sb = smem_u32(smem);
    const int tid = threadIdx.x;
    const int lane = tid & 31;
    const int wid = tid >> 5;
    const int wm = wid & 1;            // 2 warps along M (64 rows each)
    const int wn = wid >> 1;           // 4 warps along N (64 cols each)

    // ---- cp.async mapping: Ah 2 reps, Al 2 reps, B 4 reps; 8 cp16/thread ----
    const int ldRow = tid >> 2;        // 0..63
    const int ldC4 = tid & 3;
    const uint32_t sOff =
        (uint32_t)ldRow * 64 + ((((uint32_t)ldC4) ^ ((ldRow >> 1) & 3)) << 4);
    const size_t gRep = (size_t)64 * K_TOTAL;
    const __half* gAh = Ah + (size_t)(mBase + ldRow) * K_TOTAL + ldC4 * 8;
    const __half* gAl = Al + (size_t)(mBase + ldRow) * K_TOTAL + ldC4 * 8;
    const __half* gB  = Bm + (size_t)(nBase + ldRow) * K_TOTAL + ldC4 * 8;

#define ISSUE(sst, k0) do {                                                    \
        cp16((sst) + sOff,                    gAh + (k0));                      \
        cp16((sst) + sOff + 4096,             gAh + (k0) + gRep);               \
        cp16((sst) + OFF_AL + sOff,           gAl + (k0));                      \
        cp16((sst) + OFF_AL + sOff + 4096,    gAl + (k0) + gRep);               \
        cp16((sst) + OFF_B + sOff,            gB + (k0));                       \
        cp16((sst) + OFF_B + sOff + 4096,     gB + (k0) + gRep);                \
        cp16((sst) + OFF_B + sOff + 8192,     gB + (k0) + 2 * gRep);            \
        cp16((sst) + OFF_B + sOff + 12288,    gB + (k0) + 3 * gRep);            \
    } while (0)

    // ---- precomputed ldmatrix swizzle offsets (relative to stage base) ----
    uint32_t aOff[4][2];
    {
        const int rA = lane & 15;
        const uint32_t aK = (uint32_t)(lane >> 4);     // 0/1
#pragma unroll
        for (int i = 0; i < 4; i++) {
            int row = wm * 64 + i * 16 + rA;
            uint32_t base = (uint32_t)row * 64;
            uint32_t sw = (row >> 1) & 3;
#pragma unroll
            for (int kk = 0; kk < 2; kk++)
                aOff[i][kk] = base + (((aK + (uint32_t)(kk * 2)) ^ sw) << 4);
        }
    }
    uint32_t bOff[4][2];
    {
        const int rB = (lane & 7) + ((lane & 16) ? 8 : 0);
        const uint32_t bK = (uint32_t)((lane >> 3) & 1);
#pragma unroll
        for (int p = 0; p < 4; p++) {
            int row = wn * 64 + p * 16 + rB;
            uint32_t base = (uint32_t)row * 64;
            uint32_t sw = (row >> 1) & 3;
#pragma unroll
            for (int kk = 0; kk < 2; kk++)
                bOff[p][kk] = base + (((bK + (uint32_t)(kk * 2)) ^ sw) << 4);
        }
    }

    float acc[4][8][4];
#pragma unroll
    for (int i = 0; i < 4; i++)
#pragma unroll
        for (int j = 0; j < 8; j++)
#pragma unroll
            for (int v = 0; v < 4; v++) acc[i][j][v] = 0.f;

    // ---- pipeline prologue: 3 stages in flight ----
    ISSUE(sb + 0 * STG_BYTES, 0);
    CP_COMMIT();
    ISSUE(sb + 1 * STG_BYTES, BKI);
    CP_COMMIT();
    ISSUE(sb + 2 * STG_BYTES, 2 * BKI);
    CP_COMMIT();

    for (int it = 0; it < NIT; ++it) {
        CP_WAIT2();
        __syncthreads();

        if (it + 3 < NIT) {
            uint32_t sn = sb + (uint32_t)((it + 3) & 3) * STG_BYTES;
            ISSUE(sn, (it + 3) * BKI);
        }
        CP_COMMIT();

        const uint32_t sst = sb + (uint32_t)(it & 3) * STG_BYTES;
#pragma unroll
        for (int kk = 0; kk < 2; kk++) {           // two k16 halves of BK=32
            uint32_t af[16], af2[16], bf[16];

#pragma unroll
            for (int i = 0; i < 4; i++)
                ldsm_x4(&af[i * 4], sst + aOff[i][kk]);
#pragma unroll
            for (int p = 0; p < 4; p++)
                ldsm_x4(&bf[p * 4], sst + OFF_B + bOff[p][kk]);
#pragma unroll
            for (int i = 0; i < 4; i++)
#pragma unroll
                for (int j = 0; j < 8; j++)
                    mma_fp16(acc[i][j], &af[i * 4],
                             &bf[(j >> 1) * 4 + (j & 1) * 2]);

            // Al * B
#pragma unroll
            for (int i = 0; i < 4; i++)
                ldsm_x4(&af2[i * 4], sst + OFF_AL + aOff[i][kk]);
#pragma unroll
            for (int i = 0; i < 4; i++)
#pragma unroll
                for (int j = 0; j < 8; j++)
                    mma_fp16(acc[i][j], &af2[i * 4],
                             &bf[(j >> 1) * 4 + (j & 1) * 2]);
        }
    }

    // ---- epilogue: write C ----
    const int row0 = mBase + wm * 64 + (lane >> 2);
    const int col0 = nBase + wn * 64 + (lane & 3) * 2;
#pragma unroll
    for (int i = 0; i < 4; i++) {
#pragma unroll
        for (int j = 0; j < 8; j++) {
            float* p0 = C + (size_t)(row0 + i * 16) * Ntotal + col0 + j * 8;
            float* p1 = p0 + (size_t)8 * Ntotal;
            *(float2*)p0 = make_float2(acc[i][j][0], acc[i][j][1]);
            *(float2*)p1 = make_float2(acc[i][j][2], acc[i][j][3]);
        }
    }
#undef ISSUE
}

// ---------------------------------------------------------------------------
// Fused conversions (one launch, float4-vectorized):
//  seg1: hidden fp32 -> (fp16 hi, fp16 lo)
//  seg2: w_in  fp32 -> fp16
//  seg3: w_out fp32 -> fp16
// ---------------------------------------------------------------------------
#define N4_HID ((B_SZ * H_SZ) / 4)            // 1048576
#define N4_WIN ((3 * H_SZ * H_SZ) / 4)        // 3145728
#define N4_WOUT ((H_SZ * H_SZ) / 4)           // 1048576
#define N4_PREP (N4_HID + N4_WIN + N4_WOUT)

__global__ void prep_kernel(const float4* __restrict__ hidden,
                            const float4* __restrict__ w_in,
                            const float4* __restrict__ w_out,
                            __half2* __restrict__ hid_hi,
                            __half2* __restrict__ hid_lo,
                            __half2* __restrict__ win,
                            __half2* __restrict__ wout) {
    int i = blockIdx.x * blockDim.x + threadIdx.x;
    int stride = gridDim.x * blockDim.x;
    for (; i < N4_PREP; i += stride) {
        if (i < N4_HID) {
            float4 v = hidden[i];
            __half2 h0 = make_half2(__float2half_rn(v.x), __float2half_rn(v.y));
            __half2 h1 = make_half2(__float2half_rn(v.z), __float2half_rn(v.w));
            hid_hi[2 * i] = h0;
            hid_hi[2 * i + 1] = h1;
            hid_lo[2 * i] = make_half2(
                __float2half_rn(v.x - __half2float(__low2half(h0))),
                __float2half_rn(v.y - __half2float(__high2half(h0))));
            hid_lo[2 * i + 1] = make_half2(
                __float2half_rn(v.z - __half2float(__low2half(h1))),
                __float2half_rn(v.w - __half2float(__high2half(h1))));
        } else if (i < N4_HID + N4_WIN) {
            int j = i - N4_HID;
            float4 v = w_in[j];
            win[2 * j] = make_half2(__float2half_rn(v.x), __float2half_rn(v.y));
            win[2 * j + 1] = make_half2(__float2half_rn(v.z), __float2half_rn(v.w));
        } else {
            int j = i - N4_HID - N4_WIN;
            float4 v = w_out[j];
            wout[2 * j] = make_half2(__float2half_rn(v.x), __float2half_rn(v.y));
            wout[2 * j + 1] = make_half2(__float2half_rn(v.z), __float2half_rn(v.w));
        }
    }
}

// ---------------------------------------------------------------------------
// conv + gating epilogue; emits gated as fp16 hi/lo splits directly
// ---------------------------------------------------------------------------
__global__ void conv_epilogue_kernel(const float* __restrict__ proj,
                                     const float* __restrict__ conv_state,
                                     const int* __restrict__ idx,
                                     const float* __restrict__ conv_w,
                                     __half* __restrict__ ghi,
                                     __half* __restrict__ glo,
                                     float* __restrict__ out_state) {
    int i = blockIdx.x * blockDim.x + threadIdx.x;
    if (i >= B_SZ * H_SZ) return;
    int b = i >> 11;
    int h = i & (H_SZ - 1);
    int r = idx[b];

    const float* cs = conv_state + ((size_t)r * H_SZ + h) * 3;
    float c0 = cs[0], c1 = cs[1], c2 = cs[2];

    const float* prow = proj + (size_t)b * 3 * H_SZ;
    float Bg = prow[h];
    float Cg = prow[H_SZ + h];
    float x  = prow[2 * H_SZ + h];
    float Bx = Bg * x;

    const float* w = conv_w + h * 4;
    float conv_out = fmaf(c0, w[0], fmaf(c1, w[1], fmaf(c2, w[2], Bx * w[3])));
    float g = Cg * conv_out;

    __half gh = __float2half_rn(g);
    ghi[i] = gh;
    glo[i] = __float2half_rn(g - __half2float(gh));

    float* os = out_state + ((size_t)r * H_SZ + h) * 3;
    os[0] = c1;
    os[1] = c2;
    os[2] = Bx;
}

// ---------------------------------------------------------------------------
extern "C" void kernel_launch(void* const* d_in, const int* in_sizes, int n_in,
                              void* d_out, int out_size) {
    const float* hidden     = (const float*)d_in[0];
    const float* conv_state = (const float*)d_in[1];
    const int*   idx        = (const int*)d_in[2];
    const float* w_in       = (const float*)d_in[3];
    const float* w_out      = (const float*)d_in[4];
    const float* conv_w     = (const float*)d_in[5];

    float* y         = (float*)d_out;
    float* out_state = y + (size_t)B_SZ * H_SZ;

    void *proj, *hid_hi, *hid_lo, *win, *wout, *gat_hi, *gat_lo;
    cudaGetSymbolAddress(&proj, g_proj);
    cudaGetSymbolAddress(&hid_hi, g_hid_hi);
    cudaGetSymbolAddress(&hid_lo, g_hid_lo);
    cudaGetSymbolAddress(&win, g_win);
    cudaGetSymbolAddress(&wout, g_wout);
    cudaGetSymbolAddress(&gat_hi, g_gated_hi);
    cudaGetSymbolAddress(&gat_lo, g_gated_lo);

    cudaFuncSetAttribute(mma_gemm_kernel,
                         cudaFuncAttributeMaxDynamicSharedMemorySize,
                         SMEM_TOTAL);

    // 1) fused fp16 conversions (hidden split + weight casts)
    prep_kernel<<<4096, 256>>>((const float4*)hidden, (const float4*)w_in,
                               (const float4*)w_out,
                               (__half2*)hid_hi, (__half2*)hid_lo,
                               (__half2*)win, (__half2*)wout);

    // 2) GEMM1 (proj = hidden @ w_in^T, [2048 x 6144]) + interleaved
    //    conv_state copy-through on copy-role CTAs (every 4th of 512).
    {
        int nTilesN = (3 * H_SZ) / 256;                 // 24
        int gemmCTAs = nTilesN * (B_SZ / 128);          // 384
        int totalCTAs = gemmCTAs + gemmCTAs / 3;        // 512 (128 copy)
        int n4 = (P_SZ * H_SZ * 3) / 4;
        mma_gemm_kernel<<<totalCTAs, 256, SMEM_TOTAL>>>(
            (const __half*)hid_hi, (const __half*)hid_lo, (const __half*)win,
            (float*)proj, 3 * H_SZ, nTilesN,
            (const float4*)conv_state, (float4*)out_state, n4);
    }

    // 3) conv + gate epilogue -> gated (fp16 hi/lo), scatter state rows
    conv_epilogue_kernel<<<(B_SZ * H_SZ + 255) / 256, 256>>>(
        (const float*)proj, conv_state, idx, conv_w,
        (__half*)gat_hi, (__half*)gat_lo, out_state);

    // 4) y = gated @ w_out^T   [2048 x 2048], no copy role
    {
        int nTilesN = H_SZ / 256;                       // 8
        int gemmCTAs = nTilesN * (B_SZ / 128);          // 128
        mma_gemm_kernel<<<gemmCTAs, 256, SMEM_TOTAL>>>(
            (const __half*)gat_hi, (const __half*)gat_lo, (const __half*)wout,
            y, H_SZ, nTilesN, nullptr, nullptr, 0);
    }
}

// round 14
// speedup vs baseline: 1.1293x; 1.1293x over previous
#include <cuda_runtime.h>
#include <cuda_fp16.h>
#include <cstdint>

#define B_SZ 2048
#define H_SZ 2048
#define P_SZ 8192
#define K_TOTAL 2048

// ---------------------------------------------------------------------------
// Scratch (__device__ globals; no cudaMalloc allowed)
// ---------------------------------------------------------------------------
__device__ __align__(1024) float g_proj[(size_t)B_SZ * 3 * H_SZ];
__device__ __align__(1024) __half g_hid_hi[(size_t)B_SZ * H_SZ];
__device__ __align__(1024) __half g_hid_lo[(size_t)B_SZ * H_SZ];
__device__ __align__(1024) __half g_win[(size_t)3 * H_SZ * H_SZ];
__device__ __align__(1024) __half g_wout[(size_t)H_SZ * H_SZ];
__device__ __align__(1024) __half g_gated_hi[(size_t)B_SZ * H_SZ];
__device__ __align__(1024) __half g_gated_lo[(size_t)B_SZ * H_SZ];

// ---------------------------------------------------------------------------
// Baseline-PTX helpers (legal on plain sm_103 target)
// ---------------------------------------------------------------------------
__device__ __forceinline__ uint32_t smem_u32(const void* p) {
    uint32_t a;
    asm("{ .reg .u64 t; cvta.to.shared.u64 t, %1; cvt.u32.u64 %0, t; }"
        : "=r"(a) : "l"(p));
    return a;
}

__device__ __forceinline__ void cp16(uint32_t dst, const void* src) {
    asm volatile("cp.async.cg.shared.global [%0], [%1], 16;"
                 :: "r"(dst), "l"(src));
}
#define CP_COMMIT() asm volatile("cp.async.commit_group;" ::: "memory")
#define CP_WAIT2()  asm volatile("cp.async.wait_group 2;" ::: "memory")

__device__ __forceinline__ void ldsm_x4(uint32_t* r, uint32_t addr) {
    asm volatile("ldmatrix.sync.aligned.m8n8.x4.shared.b16 {%0,%1,%2,%3}, [%4];"
                 : "=r"(r[0]), "=r"(r[1]), "=r"(r[2]), "=r"(r[3]) : "r"(addr));
}

__device__ __forceinline__ void mma_fp16(float* c, const uint32_t* a,
                                         const uint32_t* b) {
    asm volatile(
        "mma.sync.aligned.m16n8k16.row.col.f32.f16.f16.f32 "
        "{%0,%1,%2,%3}, {%4,%5,%6,%7}, {%8,%9}, {%0,%1,%2,%3};"
        : "+f"(c[0]), "+f"(c[1]), "+f"(c[2]), "+f"(c[3])
        : "r"(a[0]), "r"(a[1]), "r"(a[2]), "r"(a[3]), "r"(b[0]), "r"(b[1]));
}

// ---------------------------------------------------------------------------
// Split-fp16 2-product GEMM: D = Ah*B + Al*B (A = Ah+Al fp16; err ~2^-12).
// CTA tile 128M x 128N, BK=32, 4-stage cp.async (wait_group 2), ONE
// __syncthreads per iteration. 2 CTAs/SM (launch_bounds (256,2)) -> 16
// warps/SM to cover ldmatrix->mma latency (R12 profile: tensor 57%, occ 12%).
// Stage: Ah@0(8K), Al@8K(8K), B@16K(8K) = 24KB; 4 stages = 96KB.
// Row = 64B, XOR swizzle off(r,c4)=r*64+((c4^((r>>1)&3))<<4).
// 8 warps: wm = wid&1 (64 M-rows each), wn = wid>>1 (32 N-cols each).
// Al product reuses the Ah fragment registers (B frag stays live).
// ---------------------------------------------------------------------------
#define BKI 32
#define NIT (K_TOTAL / BKI)          // 64
#define STG_BYTES 24576
#define NSTG 4
#define SMEM_TOTAL (NSTG * STG_BYTES)   // 96 KB
#define OFF_AL 8192
#define OFF_B  16384

__global__ __launch_bounds__(256, 2)
void mma_gemm_kernel(const __half* __restrict__ Ah,
                     const __half* __restrict__ Al,
                     const __half* __restrict__ Bm,
                     float* __restrict__ C, int Ntotal, int nTilesN) {
    extern __shared__ __align__(1024) char smem[];
    const uint32_t sb = smem_u32(smem);
    const int tid = threadIdx.x;
    const int lane = tid & 31;
    const int wid = tid >> 5;
    const int wm = wid & 1;            // 2 warps along M (64 rows each)
    const int wn = wid >> 1;           // 4 warps along N (32 cols each)
    const int mBase = (blockIdx.x / nTilesN) * 128;
    const int nBase = (blockIdx.x % nTilesN) * 128;

    // ---- cp.async mapping: Ah/Al/B each 128 rows -> 2 reps; 6 cp16/thread ----
    const int ldRow = tid >> 2;        // 0..63
    const int ldC4 = tid & 3;
    const uint32_t sOff =
        (uint32_t)ldRow * 64 + ((((uint32_t)ldC4) ^ ((ldRow >> 1) & 3)) << 4);
    const size_t gRep = (size_t)64 * K_TOTAL;
    const __half* gAh = Ah + (size_t)(mBase + ldRow) * K_TOTAL + ldC4 * 8;
    const __half* gAl = Al + (size_t)(mBase + ldRow) * K_TOTAL + ldC4 * 8;
    const __half* gB  = Bm + (size_t)(nBase + ldRow) * K_TOTAL + ldC4 * 8;

#define ISSUE(sst, k0) do {                                                    \
        cp16((sst) + sOff,                    gAh + (k0));                      \
        cp16((sst) + sOff + 4096,             gAh + (k0) + gRep);               \
        cp16((sst) + OFF_AL + sOff,           gAl + (k0));                      \
        cp16((sst) + OFF_AL + sOff + 4096,    gAl + (k0) + gRep);               \
        cp16((sst) + OFF_B + sOff,            gB + (k0));                       \
        cp16((sst) + OFF_B + sOff + 4096,     gB + (k0) + gRep);                \
    } while (0)

    // ---- precomputed ldmatrix swizzle offsets (relative to stage base) ----
    uint32_t aOff[4][2];
    {
        const int rA = lane & 15;
        const uint32_t aK = (uint32_t)(lane >> 4);     // 0/1
#pragma unroll
        for (int i = 0; i < 4; i++) {
            int row = wm * 64 + i * 16 + rA;
            uint32_t base = (uint32_t)row * 64;
            uint32_t sw = (row >> 1) & 3;
#pragma unroll
            for (int kk = 0; kk < 2; kk++)
                aOff[i][kk] = base + (((aK + (uint32_t)(kk * 2)) ^ sw) << 4);
        }
    }
    uint32_t bOff[2][2];
    {
        const int rB = (lane & 7) + ((lane & 16) ? 8 : 0);
        const uint32_t bK = (uint32_t)((lane >> 3) & 1);
#pragma unroll
        for (int p = 0; p < 2; p++) {
            int row = wn * 32 + p * 16 + rB;
            uint32_t base = (uint32_t)row * 64;
            uint32_t sw = (row >> 1) & 3;
#pragma unroll
            for (int kk = 0; kk < 2; kk++)
                bOff[p][kk] = base + (((bK + (uint32_t)(kk * 2)) ^ sw) << 4);
        }
    }

    float acc[4][4][4];
#pragma unroll
    for (int i = 0; i < 4; i++)
#pragma unroll
        for (int j = 0; j < 4; j++)
#pragma unroll
            for (int v = 0; v < 4; v++) acc[i][j][v] = 0.f;

    // ---- pipeline prologue: 3 stages in flight ----
    ISSUE(sb + 0 * STG_BYTES, 0);
    CP_COMMIT();
    ISSUE(sb + 1 * STG_BYTES, BKI);
    CP_COMMIT();
    ISSUE(sb + 2 * STG_BYTES, 2 * BKI);
    CP_COMMIT();

    for (int it = 0; it < NIT; ++it) {
        CP_WAIT2();
        __syncthreads();

        if (it + 3 < NIT) {
            uint32_t sn = sb + (uint32_t)((it + 3) & 3) * STG_BYTES;
            ISSUE(sn, (it + 3) * BKI);
        }
        CP_COMMIT();

        const uint32_t sst = sb + (uint32_t)(it & 3) * STG_BYTES;
#pragma unroll
        for (int kk = 0; kk < 2; kk++) {           // two k16 halves of BK=32
            uint32_t af[16], bf[8];

            // Ah * B
#pragma unroll
            for (int i = 0; i < 4; i++)
                ldsm_x4(&af[i * 4], sst + aOff[i][kk]);
#pragma unroll
            for (int p = 0; p < 2; p++)
                ldsm_x4(&bf[p * 4], sst + OFF_B + bOff[p][kk]);
#pragma unroll
            for (int i = 0; i < 4; i++)
#pragma unroll
                for (int j = 0; j < 4; j++)
                    mma_fp16(acc[i][j], &af[i * 4],
                             &bf[(j >> 1) * 4 + (j & 1) * 2]);

            // Al * B (overwrite af; bf stays live)
#pragma unroll
            for (int i = 0; i < 4; i++)
                ldsm_x4(&af[i * 4], sst + OFF_AL + aOff[i][kk]);
#pragma unroll
            for (int i = 0; i < 4; i++)
#pragma unroll
                for (int j = 0; j < 4; j++)
                    mma_fp16(acc[i][j], &af[i * 4],
                             &bf[(j >> 1) * 4 + (j & 1) * 2]);
        }
    }

    // ---- epilogue: write C ----
    const int row0 = mBase + wm * 64 + (lane >> 2);
    const int col0 = nBase + wn * 32 + (lane & 3) * 2;
#pragma unroll
    for (int i = 0; i < 4; i++) {
#pragma unroll
        for (int j = 0; j < 4; j++) {
            float* p0 = C + (size_t)(row0 + i * 16) * Ntotal + col0 + j * 8;
            float* p1 = p0 + (size_t)8 * Ntotal;
            *(float2*)p0 = make_float2(acc[i][j][0], acc[i][j][1]);
            *(float2*)p1 = make_float2(acc[i][j][2], acc[i][j][3]);
        }
    }
#undef ISSUE
}

// ---------------------------------------------------------------------------
// Fused conversions (one launch, float4-vectorized):
//  seg1: hidden fp32 -> (fp16 hi, fp16 lo); seg2: w_in -> fp16; seg3: w_out
// ---------------------------------------------------------------------------
#define N4_HID ((B_SZ * H_SZ) / 4)
#define N4_WIN ((3 * H_SZ * H_SZ) / 4)
#define N4_WOUT ((H_SZ * H_SZ) / 4)
#define N4_PREP (N4_HID + N4_WIN + N4_WOUT)

__global__ void prep_kernel(const float4* __restrict__ hidden,
                            const float4* __restrict__ w_in,
                            const float4* __restrict__ w_out,
                            __half2* __restrict__ hid_hi,
                            __half2* __restrict__ hid_lo,
                            __half2* __restrict__ win,
                            __half2* __restrict__ wout) {
    int i = blockIdx.x * blockDim.x + threadIdx.x;
    int stride = gridDim.x * blockDim.x;
    for (; i < N4_PREP; i += stride) {
        if (i < N4_HID) {
            float4 v = hidden[i];
            __half2 h0 = make_half2(__float2half_rn(v.x), __float2half_rn(v.y));
            __half2 h1 = make_half2(__float2half_rn(v.z), __float2half_rn(v.w));
            hid_hi[2 * i] = h0;
            hid_hi[2 * i + 1] = h1;
            hid_lo[2 * i] = make_half2(
                __float2half_rn(v.x - __half2float(__low2half(h0))),
                __float2half_rn(v.y - __half2float(__high2half(h0))));
            hid_lo[2 * i + 1] = make_half2(
                __float2half_rn(v.z - __half2float(__low2half(h1))),
                __float2half_rn(v.w - __half2float(__high2half(h1))));
        } else if (i < N4_HID + N4_WIN) {
            int j = i - N4_HID;
            float4 v = w_in[j];
            win[2 * j] = make_half2(__float2half_rn(v.x), __float2half_rn(v.y));
            win[2 * j + 1] = make_half2(__float2half_rn(v.z), __float2half_rn(v.w));
        } else {
            int j = i - N4_HID - N4_WIN;
            float4 v = w_out[j];
            wout[2 * j] = make_half2(__float2half_rn(v.x), __float2half_rn(v.y));
            wout[2 * j + 1] = make_half2(__float2half_rn(v.z), __float2half_rn(v.w));
        }
    }
}

// ---------------------------------------------------------------------------
// conv_state copy-through
// ---------------------------------------------------------------------------
__global__ void copy_state_kernel(const float4* __restrict__ src,
                                  float4* __restrict__ dst, int n4) {
    int i = blockIdx.x * blockDim.x + threadIdx.x;
    int stride = gridDim.x * blockDim.x;
    for (; i < n4; i += stride) dst[i] = src[i];
}

// ---------------------------------------------------------------------------
// conv + gating epilogue; emits gated as fp16 hi/lo splits directly
// ---------------------------------------------------------------------------
__global__ void conv_epilogue_kernel(const float* __restrict__ proj,
                                     const float* __restrict__ conv_state,
                                     const int* __restrict__ idx,
                                     const float* __restrict__ conv_w,
                                     __half* __restrict__ ghi,
                                     __half* __restrict__ glo,
                                     float* __restrict__ out_state) {
    int i = blockIdx.x * blockDim.x + threadIdx.x;
    if (i >= B_SZ * H_SZ) return;
    int b = i >> 11;
    int h = i & (H_SZ - 1);
    int r = idx[b];

    const float* cs = conv_state + ((size_t)r * H_SZ + h) * 3;
    float c0 = cs[0], c1 = cs[1], c2 = cs[2];

    const float* prow = proj + (size_t)b * 3 * H_SZ;
    float Bg = prow[h];
    float Cg = prow[H_SZ + h];
    float x  = prow[2 * H_SZ + h];
    float Bx = Bg * x;

    const float* w = conv_w + h * 4;
    float conv_out = fmaf(c0, w[0], fmaf(c1, w[1], fmaf(c2, w[2], Bx * w[3])));
    float g = Cg * conv_out;

    __half gh = __float2half_rn(g);
    ghi[i] = gh;
    glo[i] = __float2half_rn(g - __half2float(gh));

    float* os = out_state + ((size_t)r * H_SZ + h) * 3;
    os[0] = c1;
    os[1] = c2;
    os[2] = Bx;
}

// ---------------------------------------------------------------------------
extern "C" void kernel_launch(void* const* d_in, const int* in_sizes, int n_in,
                              void* d_out, int out_size) {
    const float* hidden     = (const float*)d_in[0];
    const float* conv_state = (const float*)d_in[1];
    const int*   idx        = (const int*)d_in[2];
    const float* w_in       = (const float*)d_in[3];
    const float* w_out      = (const float*)d_in[4];
    const float* conv_w     = (const float*)d_in[5];

    float* y         = (float*)d_out;
    float* out_state = y + (size_t)B_SZ * H_SZ;

    void *proj, *hid_hi, *hid_lo, *win, *wout, *gat_hi, *gat_lo;
    cudaGetSymbolAddress(&proj, g_proj);
    cudaGetSymbolAddress(&hid_hi, g_hid_hi);
    cudaGetSymbolAddress(&hid_lo, g_hid_lo);
    cudaGetSymbolAddress(&win, g_win);
    cudaGetSymbolAddress(&wout, g_wout);
    cudaGetSymbolAddress(&gat_hi, g_gated_hi);
    cudaGetSymbolAddress(&gat_lo, g_gated_lo);

    cudaFuncSetAttribute(mma_gemm_kernel,
                         cudaFuncAttributeMaxDynamicSharedMemorySize,
                         SMEM_TOTAL);

    // 1) fused fp16 conversions (hidden split + weight casts)
    prep_kernel<<<4096, 256>>>((const float4*)hidden, (const float4*)w_in,
                               (const float4*)w_out,
                               (__half2*)hid_hi, (__half2*)hid_lo,
                               (__half2*)win, (__half2*)wout);

    // 2) conv_state copy-through (rows overwritten by epilogue)
    copy_state_kernel<<<4096, 256>>>((const float4*)conv_state,
                                     (float4*)out_state, (P_SZ * H_SZ * 3) / 4);

    // 3) proj = hidden @ w_in^T   [2048 x 6144]
    {
        int nTilesN = (3 * H_SZ) / 128;                 // 48
        int gemmCTAs = nTilesN * (B_SZ / 128);          // 768
        mma_gemm_kernel<<<gemmCTAs, 256, SMEM_TOTAL>>>(
            (const __half*)hid_hi, (const __half*)hid_lo, (const __half*)win,
            (float*)proj, 3 * H_SZ, nTilesN);
    }

    // 4) conv + gate epilogue -> gated (fp16 hi/lo), scatter state rows
    conv_epilogue_kernel<<<(B_SZ * H_SZ + 255) / 256, 256>>>(
        (const float*)proj, conv_state, idx, conv_w,
        (__half*)gat_hi, (__half*)gat_lo, out_state);

    // 5) y = gated @ w_out^T   [2048 x 2048]
    {
        int nTilesN = H_SZ / 128;                       // 16
        int gemmCTAs = nTilesN * (B_SZ / 128);          // 256
        mma_gemm_kernel<<<gemmCTAs, 256, SMEM_TOTAL>>>(
            (const __half*)gat_hi, (const __half*)gat_lo, (const __half*)wout,
            y, H_SZ, nTilesN);
    }
}

// round 15
// speedup vs baseline: 1.1321x; 1.0024x over previous
#include <cuda_runtime.h>
#include <cuda_fp16.h>
#include <cstdint>

#define B_SZ 2048
#define H_SZ 2048
#define P_SZ 8192
#define K_TOTAL 2048

// ---------------------------------------------------------------------------
// Scratch (__device__ globals; no cudaMalloc allowed)
// ---------------------------------------------------------------------------
__device__ __align__(1024) float g_proj[(size_t)B_SZ * 3 * H_SZ];
__device__ __align__(1024) __half g_hid_hi[(size_t)B_SZ * H_SZ];
__device__ __align__(1024) __half g_hid_lo[(size_t)B_SZ * H_SZ];
__device__ __align__(1024) __half g_win[(size_t)3 * H_SZ * H_SZ];
__device__ __align__(1024) __half g_wout[(size_t)H_SZ * H_SZ];
__device__ __align__(1024) __half g_gated_hi[(size_t)B_SZ * H_SZ];
__device__ __align__(1024) __half g_gated_lo[(size_t)B_SZ * H_SZ];

// ---------------------------------------------------------------------------
// Baseline-PTX helpers (legal on plain sm_103 target)
// ---------------------------------------------------------------------------
__device__ __forceinline__ uint32_t smem_u32(const void* p) {
    uint32_t a;
    asm("{ .reg .u64 t; cvta.to.shared.u64 t, %1; cvt.u32.u64 %0, t; }"
        : "=r"(a) : "l"(p));
    return a;
}

__device__ __forceinline__ void cp16(uint32_t dst, const void* src) {
    asm volatile("cp.async.cg.shared.global [%0], [%1], 16;"
                 :: "r"(dst), "l"(src));
}
#define CP_COMMIT() asm volatile("cp.async.commit_group;" ::: "memory")
#define CP_WAIT2()  asm volatile("cp.async.wait_group 2;" ::: "memory")

__device__ __forceinline__ void ldsm_x4(uint32_t* r, uint32_t addr) {
    asm volatile("ldmatrix.sync.aligned.m8n8.x4.shared.b16 {%0,%1,%2,%3}, [%4];"
                 : "=r"(r[0]), "=r"(r[1]), "=r"(r[2]), "=r"(r[3]) : "r"(addr));
}

__device__ __forceinline__ void mma_fp16(float* c, const uint32_t* a,
                                         const uint32_t* b) {
    asm volatile(
        "mma.sync.aligned.m16n8k16.row.col.f32.f16.f16.f32 "
        "{%0,%1,%2,%3}, {%4,%5,%6,%7}, {%8,%9}, {%0,%1,%2,%3};"
        : "+f"(c[0]), "+f"(c[1]), "+f"(c[2]), "+f"(c[3])
        : "r"(a[0]), "r"(a[1]), "r"(a[2]), "r"(a[3]), "r"(b[0]), "r"(b[1]));
}

// ---------------------------------------------------------------------------
// Split-fp16 2-product GEMM: D = Ah*B + Al*B (A = Ah+Al fp16; err ~2^-12).
// CTA tile 128M x 128N, BK=32, 4-stage cp.async (wait_group 2), ONE
// __syncthreads per iteration. 2 CTAs/SM -> 16 warps/SM (R13: fixed the
// latency-bound tensor pipe, 57% -> higher).
// Stage: Ah@0(8K), Al@8K(8K), B@16K(8K) = 24KB; 4 stages = 96KB.
// Row = 64B, XOR swizzle off(r,c4)=r*64+((c4^((r>>1)&3))<<4).
// 8 warps: wm = wid&1 (64 M-rows each), wn = wid>>1 (32 N-cols each).
// ---------------------------------------------------------------------------
#define BKI 32
#define NIT (K_TOTAL / BKI)          // 64
#define STG_BYTES 24576
#define NSTG 4
#define SMEM_TOTAL (NSTG * STG_BYTES)   // 96 KB
#define OFF_AL 8192
#define OFF_B  16384

__global__ __launch_bounds__(256, 2)
void mma_gemm_kernel(const __half* __restrict__ Ah,
                     const __half* __restrict__ Al,
                     const __half* __restrict__ Bm,
                     float* __restrict__ C, int Ntotal, int nTilesN) {
    extern __shared__ __align__(1024) char smem[];
    const uint32_t sb = smem_u32(smem);
    const int tid = threadIdx.x;
    const int lane = tid & 31;
    const int wid = tid >> 5;
    const int wm = wid & 1;            // 2 warps along M (64 rows each)
    const int wn = wid >> 1;           // 4 warps along N (32 cols each)
    const int mBase = (blockIdx.x / nTilesN) * 128;
    const int nBase = (blockIdx.x % nTilesN) * 128;

    // ---- cp.async mapping: Ah/Al/B each 128 rows -> 2 reps; 6 cp16/thread ----
    const int ldRow = tid >> 2;        // 0..63
    const int ldC4 = tid & 3;
    const uint32_t sOff =
        (uint32_t)ldRow * 64 + ((((uint32_t)ldC4) ^ ((ldRow >> 1) & 3)) << 4);
    const size_t gRep = (size_t)64 * K_TOTAL;
    const __half* gAh = Ah + (size_t)(mBase + ldRow) * K_TOTAL + ldC4 * 8;
    const __half* gAl = Al + (size_t)(mBase + ldRow) * K_TOTAL + ldC4 * 8;
    const __half* gB  = Bm + (size_t)(nBase + ldRow) * K_TOTAL + ldC4 * 8;

#define ISSUE(sst, k0) do {                                                    \
        cp16((sst) + sOff,                    gAh + (k0));                      \
        cp16((sst) + sOff + 4096,             gAh + (k0) + gRep);               \
        cp16((sst) + OFF_AL + sOff,           gAl + (k0));                      \
        cp16((sst) + OFF_AL + sOff + 4096,    gAl + (k0) + gRep);               \
        cp16((sst) + OFF_B + sOff,            gB + (k0));                       \
        cp16((sst) + OFF_B + sOff + 4096,     gB + (k0) + gRep);                \
    } while (0)

    // ---- precomputed ldmatrix swizzle offsets (relative to stage base) ----
    uint32_t aOff[4][2];
    {
        const int rA = lane & 15;
        const uint32_t aK = (uint32_t)(lane >> 4);     // 0/1
#pragma unroll
        for (int i = 0; i < 4; i++) {
            int row = wm * 64 + i * 16 + rA;
            uint32_t base = (uint32_t)row * 64;
            uint32_t sw = (row >> 1) & 3;
#pragma unroll
            for (int kk = 0; kk < 2; kk++)
                aOff[i][kk] = base + (((aK + (uint32_t)(kk * 2)) ^ sw) << 4);
        }
    }
    uint32_t bOff[2][2];
    {
        const int rB = (lane & 7) + ((lane & 16) ? 8 : 0);
        const uint32_t bK = (uint32_t)((lane >> 3) & 1);
#pragma unroll
        for (int p = 0; p < 2; p++) {
            int row = wn * 32 + p * 16 + rB;
            uint32_t base = (uint32_t)row * 64;
            uint32_t sw = (row >> 1) & 3;
#pragma unroll
            for (int kk = 0; kk < 2; kk++)
                bOff[p][kk] = base + (((bK + (uint32_t)(kk * 2)) ^ sw) << 4);
        }
    }

    float acc[4][4][4];
#pragma unroll
    for (int i = 0; i < 4; i++)
#pragma unroll
        for (int j = 0; j < 4; j++)
#pragma unroll
            for (int v = 0; v < 4; v++) acc[i][j][v] = 0.f;

    // ---- pipeline prologue: 3 stages in flight ----
    ISSUE(sb + 0 * STG_BYTES, 0);
    CP_COMMIT();
    ISSUE(sb + 1 * STG_BYTES, BKI);
    CP_COMMIT();
    ISSUE(sb + 2 * STG_BYTES, 2 * BKI);
    CP_COMMIT();

    for (int it = 0; it < NIT; ++it) {
        CP_WAIT2();
        __syncthreads();

        if (it + 3 < NIT) {
            uint32_t sn = sb + (uint32_t)((it + 3) & 3) * STG_BYTES;
            ISSUE(sn, (it + 3) * BKI);
        }
        CP_COMMIT();

        const uint32_t sst = sb + (uint32_t)(it & 3) * STG_BYTES;
#pragma unroll
        for (int kk = 0; kk < 2; kk++) {           // two k16 halves of BK=32
            uint32_t af[16], bf[8];

            // Ah * B
#pragma unroll
            for (int i = 0; i < 4; i++)
                ldsm_x4(&af[i * 4], sst + aOff[i][kk]);
#pragma unroll
            for (int p = 0; p < 2; p++)
                ldsm_x4(&bf[p * 4], sst + OFF_B + bOff[p][kk]);
#pragma unroll
            for (int i = 0; i < 4; i++)
#pragma unroll
                for (int j = 0; j < 4; j++)
                    mma_fp16(acc[i][j], &af[i * 4],
                             &bf[(j >> 1) * 4 + (j & 1) * 2]);

            // Al * B (overwrite af; bf stays live)
#pragma unroll
            for (int i = 0; i < 4; i++)
                ldsm_x4(&af[i * 4], sst + OFF_AL + aOff[i][kk]);
#pragma unroll
            for (int i = 0; i < 4; i++)
#pragma unroll
                for (int j = 0; j < 4; j++)
                    mma_fp16(acc[i][j], &af[i * 4],
                             &bf[(j >> 1) * 4 + (j & 1) * 2]);
        }
    }

    // ---- epilogue: write C ----
    const int row0 = mBase + wm * 64 + (lane >> 2);
    const int col0 = nBase + wn * 32 + (lane & 3) * 2;
#pragma unroll
    for (int i = 0; i < 4; i++) {
#pragma unroll
        for (int j = 0; j < 4; j++) {
            float* p0 = C + (size_t)(row0 + i * 16) * Ntotal + col0 + j * 8;
            float* p1 = p0 + (size_t)8 * Ntotal;
            *(float2*)p0 = make_float2(acc[i][j][0], acc[i][j][1]);
            *(float2*)p1 = make_float2(acc[i][j][2], acc[i][j][3]);
        }
    }
#undef ISSUE
}

// ---------------------------------------------------------------------------
// Fused conversions (one launch, float4-vectorized)
// ---------------------------------------------------------------------------
#define N4_HID ((B_SZ * H_SZ) / 4)
#define N4_WIN ((3 * H_SZ * H_SZ) / 4)
#define N4_WOUT ((H_SZ * H_SZ) / 4)
#define N4_PREP (N4_HID + N4_WIN + N4_WOUT)

__global__ void prep_kernel(const float4* __restrict__ hidden,
                            const float4* __restrict__ w_in,
                            const float4* __restrict__ w_out,
                            __half2* __restrict__ hid_hi,
                            __half2* __restrict__ hid_lo,
                            __half2* __restrict__ win,
                            __half2* __restrict__ wout) {
    int i = blockIdx.x * blockDim.x + threadIdx.x;
    int stride = gridDim.x * blockDim.x;
    for (; i < N4_PREP; i += stride) {
        if (i < N4_HID) {
            float4 v = hidden[i];
            __half2 h0 = make_half2(__float2half_rn(v.x), __float2half_rn(v.y));
            __half2 h1 = make_half2(__float2half_rn(v.z), __float2half_rn(v.w));
            hid_hi[2 * i] = h0;
            hid_hi[2 * i + 1] = h1;
            hid_lo[2 * i] = make_half2(
                __float2half_rn(v.x - __half2float(__low2half(h0))),
                __float2half_rn(v.y - __half2float(__high2half(h0))));
            hid_lo[2 * i + 1] = make_half2(
                __float2half_rn(v.z - __half2float(__low2half(h1))),
                __float2half_rn(v.w - __half2float(__high2half(h1))));
        } else if (i < N4_HID + N4_WIN) {
            int j = i - N4_HID;
            float4 v = w_in[j];
            win[2 * j] = make_half2(__float2half_rn(v.x), __float2half_rn(v.y));
            win[2 * j + 1] = make_half2(__float2half_rn(v.z), __float2half_rn(v.w));
        } else {
            int j = i - N4_HID - N4_WIN;
            float4 v = w_out[j];
            wout[2 * j] = make_half2(__float2half_rn(v.x), __float2half_rn(v.y));
            wout[2 * j + 1] = make_half2(__float2half_rn(v.z), __float2half_rn(v.w));
        }
    }
}

// ---------------------------------------------------------------------------
// conv_state copy-through (zero smem -> co-schedules with GEMM CTAs)
// ---------------------------------------------------------------------------
__global__ void copy_state_kernel(const float4* __restrict__ src,
                                  float4* __restrict__ dst, int n4) {
    int i = blockIdx.x * blockDim.x + threadIdx.x;
    int stride = gridDim.x * blockDim.x;
    for (; i < n4; i += stride) dst[i] = src[i];
}

// ---------------------------------------------------------------------------
// conv + gating epilogue, 4-wide over h (float4 path); emits gated fp16 hi/lo
// ---------------------------------------------------------------------------
__global__ void conv_epilogue_kernel(const float* __restrict__ proj,
                                     const float* __restrict__ conv_state,
                                     const int* __restrict__ idx,
                                     const float* __restrict__ conv_w,
                                     __half2* __restrict__ ghi,
                                     __half2* __restrict__ glo,
                                     float* __restrict__ out_state) {
    int t = blockIdx.x * blockDim.x + threadIdx.x;
    if (t >= (B_SZ * H_SZ) / 4) return;
    int b = t >> 9;                 // / (H_SZ/4)
    int h = (t & 511) << 2;         // 4-aligned h
    int r = idx[b];

    const float4* cs =
        (const float4*)(conv_state + ((size_t)r * H_SZ + h) * 3);
    float4 ca = cs[0];   // h0:{c0,c1,c2} h1:{c0}
    float4 cb = cs[1];   // h1:{c1,c2}  h2:{c0,c1}
    float4 cc = cs[2];   // h2:{c2}     h3:{c0,c1,c2}

    const float* prow = proj + (size_t)b * 3 * H_SZ;
    float4 Bg = *(const float4*)(prow + h);
    float4 Cg = *(const float4*)(prow + H_SZ + h);
    float4 xx = *(const float4*)(prow + 2 * H_SZ + h);

    const float4* wv = (const float4*)(conv_w + h * 4);
    float4 w0 = wv[0], w1 = wv[1], w2 = wv[2], w3 = wv[3];

    float Bx0 = Bg.x * xx.x, Bx1 = Bg.y * xx.y;
    float Bx2 = Bg.z * xx.z, Bx3 = Bg.w * xx.w;

    float g0 = Cg.x * fmaf(ca.x, w0.x, fmaf(ca.y, w0.y, fmaf(ca.z, w0.z, Bx0 * w0.w)));
    float g1 = Cg.y * fmaf(ca.w, w1.x, fmaf(cb.x, w1.y, fmaf(cb.y, w1.z, Bx1 * w1.w)));
    float g2 = Cg.z * fmaf(cb.z, w2.x, fmaf(cb.w, w2.y, fmaf(cc.x, w2.z, Bx2 * w2.w)));
    float g3 = Cg.w * fmaf(cc.y, w3.x, fmaf(cc.z, w3.y, fmaf(cc.w, w3.z, Bx3 * w3.w)));

    __half h0 = __float2half_rn(g0), h1 = __float2half_rn(g1);
    __half h2 = __float2half_rn(g2), h3 = __float2half_rn(g3);
    ghi[2 * t]     = make_half2(h0, h1);
    ghi[2 * t + 1] = make_half2(h2, h3);
    glo[2 * t] = make_half2(__float2half_rn(g0 - __half2float(h0)),
                            __float2half_rn(g1 - __half2float(h1)));
    glo[2 * t + 1] = make_half2(__float2half_rn(g2 - __half2float(h2)),
                                __float2half_rn(g3 - __half2float(h3)));

    float4* os = (float4*)(out_state + ((size_t)r * H_SZ + h) * 3);
    os[0] = make_float4(ca.y, ca.z, Bx0, cb.x);
    os[1] = make_float4(cb.y, Bx1, cb.w, cc.x);
    os[2] = make_float4(Bx2, cc.z, cc.w, Bx3);
}

// ---------------------------------------------------------------------------
extern "C" void kernel_launch(void* const* d_in, const int* in_sizes, int n_in,
                              void* d_out, int out_size) {
    const float* hidden     = (const float*)d_in[0];
    const float* conv_state = (const float*)d_in[1];
    const int*   idx        = (const int*)d_in[2];
    const float* w_in       = (const float*)d_in[3];
    const float* w_out      = (const float*)d_in[4];
    const float* conv_w     = (const float*)d_in[5];

    float* y         = (float*)d_out;
    float* out_state = y + (size_t)B_SZ * H_SZ;

    void *proj, *hid_hi, *hid_lo, *win, *wout, *gat_hi, *gat_lo;
    cudaGetSymbolAddress(&proj, g_proj);
    cudaGetSymbolAddress(&hid_hi, g_hid_hi);
    cudaGetSymbolAddress(&hid_lo, g_hid_lo);
    cudaGetSymbolAddress(&win, g_win);
    cudaGetSymbolAddress(&wout, g_wout);
    cudaGetSymbolAddress(&gat_hi, g_gated_hi);
    cudaGetSymbolAddress(&gat_lo, g_gated_lo);

    cudaFuncSetAttribute(mma_gemm_kernel,
                         cudaFuncAttributeMaxDynamicSharedMemorySize,
                         SMEM_TOTAL);

    // Side stream + fork/join events (fresh per call; host-side only, the
    // cross-stream edges are captured as graph dependencies).
    cudaStream_t side;
    cudaStreamCreateWithFlags(&side, cudaStreamNonBlocking);
    cudaEvent_t evFork, evJoin;
    cudaEventCreateWithFlags(&evFork, cudaEventDisableTiming);
    cudaEventCreateWithFlags(&evJoin, cudaEventDisableTiming);

    // fork: copy_state runs concurrently with prep + GEMM1 (zero-smem CTAs
    // co-schedule onto SMs holding GEMM CTAs; DRAM vs tensor pipe).
    cudaEventRecord(evFork, 0);
    cudaStreamWaitEvent(side, evFork, 0);
    copy_state_kernel<<<4096, 256, 0, side>>>(
        (const float4*)conv_state, (float4*)out_state, (P_SZ * H_SZ * 3) / 4);
    cudaEventRecord(evJoin, side);

    // main stream: prep -> GEMM1
    prep_kernel<<<4096, 256>>>((const float4*)hidden, (const float4*)w_in,
                               (const float4*)w_out,
                               (__half2*)hid_hi, (__half2*)hid_lo,
                               (__half2*)win, (__half2*)wout);
    {
        int nTilesN = (3 * H_SZ) / 128;                 // 48
        int gemmCTAs = nTilesN * (B_SZ / 128);          // 768
        mma_gemm_kernel<<<gemmCTAs, 256, SMEM_TOTAL>>>(
            (const __half*)hid_hi, (const __half*)hid_lo, (const __half*)win,
            (float*)proj, 3 * H_SZ, nTilesN);
    }

    // join: epilogue overwrites scattered rows -> must follow the copy
    cudaStreamWaitEvent(0, evJoin, 0);
    conv_epilogue_kernel<<<(B_SZ * H_SZ / 4 + 255) / 256, 256>>>(
        (const float*)proj, conv_state, idx, conv_w,
        (__half2*)gat_hi, (__half2*)gat_lo, out_state);

    // GEMM2: y = gated @ w_out^T   [2048 x 2048]
    {
        int nTilesN = H_SZ / 128;                       // 16
        int gemmCTAs = nTilesN * (B_SZ / 128);          // 256
        mma_gemm_kernel<<<gemmCTAs, 256, SMEM_TOTAL>>>(
            (const __half*)gat_hi, (const __half*)gat_lo, (const __half*)wout,
            y, H_SZ, nTilesN);
    }
}

// round 16
// speedup vs baseline: 1.1415x; 1.0083x over previous
#include <cuda_runtime.h>
#include <cuda_fp16.h>
#include <cstdint>

#define B_SZ 2048
#define H_SZ 2048
#define P_SZ 8192
#define K_TOTAL 2048

// ---------------------------------------------------------------------------
// Scratch (__device__ globals; no cudaMalloc allowed)
// ---------------------------------------------------------------------------
__device__ __align__(1024) float g_proj[(size_t)B_SZ * 3 * H_SZ];
__device__ __align__(1024) __half g_hid_hi[(size_t)B_SZ * H_SZ];
__device__ __align__(1024) __half g_hid_lo[(size_t)B_SZ * H_SZ];
__device__ __align__(1024) __half g_win[(size_t)3 * H_SZ * H_SZ];
__device__ __align__(1024) __half g_wout[(size_t)H_SZ * H_SZ];
__device__ __align__(1024) __half g_gated_hi[(size_t)B_SZ * H_SZ];
__device__ __align__(1024) __half g_gated_lo[(size_t)B_SZ * H_SZ];

// ---------------------------------------------------------------------------
// Baseline-PTX helpers (legal on plain sm_103 target)
// ---------------------------------------------------------------------------
__device__ __forceinline__ uint32_t smem_u32(const void* p) {
    uint32_t a;
    asm("{ .reg .u64 t; cvta.to.shared.u64 t, %1; cvt.u32.u64 %0, t; }"
        : "=r"(a) : "l"(p));
    return a;
}

__device__ __forceinline__ void cp16(uint32_t dst, const void* src) {
    asm volatile("cp.async.cg.shared.global [%0], [%1], 16;"
                 :: "r"(dst), "l"(src));
}
#define CP_COMMIT() asm volatile("cp.async.commit_group;" ::: "memory")
#define CP_WAIT2()  asm volatile("cp.async.wait_group 2;" ::: "memory")

__device__ __forceinline__ void ldsm_x4(uint32_t* r, uint32_t addr) {
    asm volatile("ldmatrix.sync.aligned.m8n8.x4.shared.b16 {%0,%1,%2,%3}, [%4];"
                 : "=r"(r[0]), "=r"(r[1]), "=r"(r[2]), "=r"(r[3]) : "r"(addr));
}

__device__ __forceinline__ void mma_fp16(float* c, const uint32_t* a,
                                         const uint32_t* b) {
    asm volatile(
        "mma.sync.aligned.m16n8k16.row.col.f32.f16.f16.f32 "
        "{%0,%1,%2,%3}, {%4,%5,%6,%7}, {%8,%9}, {%0,%1,%2,%3};"
        : "+f"(c[0]), "+f"(c[1]), "+f"(c[2]), "+f"(c[3])
        : "r"(a[0]), "r"(a[1]), "r"(a[2]), "r"(a[3]), "r"(b[0]), "r"(b[1]));
}

// ---------------------------------------------------------------------------
// Split-fp16 2-product GEMM: D = Ah*B + Al*B (A = Ah+Al fp16; err ~2^-12).
// CTA tile 128M x 128N, BK=32, 4-stage cp.async (wait_group 2), ONE
// __syncthreads per iteration. 2 CTAs/SM -> 16 warps/SM.
// Stage: Ah@0(8K), Al@8K(8K), B@16K(8K) = 24KB; 4 stages = 96KB.
// Row = 64B, XOR swizzle off(r,c4)=r*64+((c4^((r>>1)&3))<<4).
// 8 warps: wm = wid&1 (64 M-rows each), wn = wid>>1 (32 N-cols each).
// ---------------------------------------------------------------------------
#define BKI 32
#define NIT (K_TOTAL / BKI)          // 64
#define STG_BYTES 24576
#define NSTG 4
#define SMEM_TOTAL (NSTG * STG_BYTES)   // 96 KB
#define OFF_AL 8192
#define OFF_B  16384

__global__ __launch_bounds__(256, 2)
void mma_gemm_kernel(const __half* __restrict__ Ah,
                     const __half* __restrict__ Al,
                     const __half* __restrict__ Bm,
                     float* __restrict__ C, int Ntotal, int nTilesN) {
    extern __shared__ __align__(1024) char smem[];
    const uint32_t sb = smem_u32(smem);
    const int tid = threadIdx.x;
    const int lane = tid & 31;
    const int wid = tid >> 5;
    const int wm = wid & 1;            // 2 warps along M (64 rows each)
    const int wn = wid >> 1;           // 4 warps along N (32 cols each)
    const int mBase = (blockIdx.x / nTilesN) * 128;
    const int nBase = (blockIdx.x % nTilesN) * 128;

    // ---- cp.async mapping: Ah/Al/B each 128 rows -> 2 reps; 6 cp16/thread ----
    const int ldRow = tid >> 2;        // 0..63
    const int ldC4 = tid & 3;
    const uint32_t sOff =
        (uint32_t)ldRow * 64 + ((((uint32_t)ldC4) ^ ((ldRow >> 1) & 3)) << 4);
    const size_t gRep = (size_t)64 * K_TOTAL;
    const __half* gAh = Ah + (size_t)(mBase + ldRow) * K_TOTAL + ldC4 * 8;
    const __half* gAl = Al + (size_t)(mBase + ldRow) * K_TOTAL + ldC4 * 8;
    const __half* gB  = Bm + (size_t)(nBase + ldRow) * K_TOTAL + ldC4 * 8;

#define ISSUE(sst, k0) do {                                                    \
        cp16((sst) + sOff,                    gAh + (k0));                      \
        cp16((sst) + sOff + 4096,             gAh + (k0) + gRep);               \
        cp16((sst) + OFF_AL + sOff,           gAl + (k0));                      \
        cp16((sst) + OFF_AL + sOff + 4096,    gAl + (k0) + gRep);               \
        cp16((sst) + OFF_B + sOff,            gB + (k0));                       \
        cp16((sst) + OFF_B + sOff + 4096,     gB + (k0) + gRep);                \
    } while (0)

    // ---- precomputed ldmatrix swizzle offsets (relative to stage base) ----
    uint32_t aOff[4][2];
    {
        const int rA = lane & 15;
        const uint32_t aK = (uint32_t)(lane >> 4);     // 0/1
#pragma unroll
        for (int i = 0; i < 4; i++) {
            int row = wm * 64 + i * 16 + rA;
            uint32_t base = (uint32_t)row * 64;
            uint32_t sw = (row >> 1) & 3;
#pragma unroll
            for (int kk = 0; kk < 2; kk++)
                aOff[i][kk] = base + (((aK + (uint32_t)(kk * 2)) ^ sw) << 4);
        }
    }
    uint32_t bOff[2][2];
    {
        const int rB = (lane & 7) + ((lane & 16) ? 8 : 0);
        const uint32_t bK = (uint32_t)((lane >> 3) & 1);
#pragma unroll
        for (int p = 0; p < 2; p++) {
            int row = wn * 32 + p * 16 + rB;
            uint32_t base = (uint32_t)row * 64;
            uint32_t sw = (row >> 1) & 3;
#pragma unroll
            for (int kk = 0; kk < 2; kk++)
                bOff[p][kk] = base + (((bK + (uint32_t)(kk * 2)) ^ sw) << 4);
        }
    }

    float acc[4][4][4];
#pragma unroll
    for (int i = 0; i < 4; i++)
#pragma unroll
        for (int j = 0; j < 4; j++)
#pragma unroll
            for (int v = 0; v < 4; v++) acc[i][j][v] = 0.f;

    // ---- pipeline prologue: 3 stages in flight ----
    ISSUE(sb + 0 * STG_BYTES, 0);
    CP_COMMIT();
    ISSUE(sb + 1 * STG_BYTES, BKI);
    CP_COMMIT();
    ISSUE(sb + 2 * STG_BYTES, 2 * BKI);
    CP_COMMIT();

    for (int it = 0; it < NIT; ++it) {
        CP_WAIT2();
        __syncthreads();

        if (it + 3 < NIT) {
            uint32_t sn = sb + (uint32_t)((it + 3) & 3) * STG_BYTES;
            ISSUE(sn, (it + 3) * BKI);
        }
        CP_COMMIT();

        const uint32_t sst = sb + (uint32_t)(it & 3) * STG_BYTES;
#pragma unroll
        for (int kk = 0; kk < 2; kk++) {           // two k16 halves of BK=32
            uint32_t af[16], bf[8];

            // Ah * B
#pragma unroll
            for (int i = 0; i < 4; i++)
                ldsm_x4(&af[i * 4], sst + aOff[i][kk]);
#pragma unroll
            for (int p = 0; p < 2; p++)
                ldsm_x4(&bf[p * 4], sst + OFF_B + bOff[p][kk]);
#pragma unroll
            for (int i = 0; i < 4; i++)
#pragma unroll
                for (int j = 0; j < 4; j++)
                    mma_fp16(acc[i][j], &af[i * 4],
                             &bf[(j >> 1) * 4 + (j & 1) * 2]);

            // Al * B (overwrite af; bf stays live)
#pragma unroll
            for (int i = 0; i < 4; i++)
                ldsm_x4(&af[i * 4], sst + OFF_AL + aOff[i][kk]);
#pragma unroll
            for (int i = 0; i < 4; i++)
#pragma unroll
                for (int j = 0; j < 4; j++)
                    mma_fp16(acc[i][j], &af[i * 4],
                             &bf[(j >> 1) * 4 + (j & 1) * 2]);
        }
    }

    // ---- epilogue: write C ----
    const int row0 = mBase + wm * 64 + (lane >> 2);
    const int col0 = nBase + wn * 32 + (lane & 3) * 2;
#pragma unroll
    for (int i = 0; i < 4; i++) {
#pragma unroll
        for (int j = 0; j < 4; j++) {
            float* p0 = C + (size_t)(row0 + i * 16) * Ntotal + col0 + j * 8;
            float* p1 = p0 + (size_t)8 * Ntotal;
            *(float2*)p0 = make_float2(acc[i][j][0], acc[i][j][1]);
            *(float2*)p1 = make_float2(acc[i][j][2], acc[i][j][3]);
        }
    }
#undef ISSUE
}

// ---------------------------------------------------------------------------
// Fused conversions (one launch, float4-vectorized)
// ---------------------------------------------------------------------------
#define N4_HID ((B_SZ * H_SZ) / 4)
#define N4_WIN ((3 * H_SZ * H_SZ) / 4)
#define N4_WOUT ((H_SZ * H_SZ) / 4)
#define N4_PREP (N4_HID + N4_WIN + N4_WOUT)

__global__ void prep_kernel(const float4* __restrict__ hidden,
                            const float4* __restrict__ w_in,
                            const float4* __restrict__ w_out,
                            __half2* __restrict__ hid_hi,
                            __half2* __restrict__ hid_lo,
                            __half2* __restrict__ win,
                            __half2* __restrict__ wout) {
    int i = blockIdx.x * blockDim.x + threadIdx.x;
    int stride = gridDim.x * blockDim.x;
    for (; i < N4_PREP; i += stride) {
        if (i < N4_HID) {
            float4 v = hidden[i];
            __half2 h0 = make_half2(__float2half_rn(v.x), __float2half_rn(v.y));
            __half2 h1 = make_half2(__float2half_rn(v.z), __float2half_rn(v.w));
            hid_hi[2 * i] = h0;
            hid_hi[2 * i + 1] = h1;
            hid_lo[2 * i] = make_half2(
                __float2half_rn(v.x - __half2float(__low2half(h0))),
                __float2half_rn(v.y - __half2float(__high2half(h0))));
            hid_lo[2 * i + 1] = make_half2(
                __float2half_rn(v.z - __half2float(__low2half(h1))),
                __float2half_rn(v.w - __half2float(__high2half(h1))));
        } else if (i < N4_HID + N4_WIN) {
            int j = i - N4_HID;
            float4 v = w_in[j];
            win[2 * j] = make_half2(__float2half_rn(v.x), __float2half_rn(v.y));
            win[2 * j + 1] = make_half2(__float2half_rn(v.z), __float2half_rn(v.w));
        } else {
            int j = i - N4_HID - N4_WIN;
            float4 v = w_out[j];
            wout[2 * j] = make_half2(__float2half_rn(v.x), __float2half_rn(v.y));
            wout[2 * j + 1] = make_half2(__float2half_rn(v.z), __float2half_rn(v.w));
        }
    }
}

// ---------------------------------------------------------------------------
// conv_state copy-through: SMALL grid (2 CTAs/SM) so it co-resides with the
// GEMM CTAs instead of flooding the device (R14 lesson). Unroll 4 for MLP.
// ---------------------------------------------------------------------------
__global__ void copy_state_kernel(const float4* __restrict__ src,
                                  float4* __restrict__ dst, int n4) {
    int i = blockIdx.x * blockDim.x + threadIdx.x;
    int stride = gridDim.x * blockDim.x;
#pragma unroll 4
    for (; i < n4; i += stride) dst[i] = src[i];
}

// ---------------------------------------------------------------------------
// conv + gating epilogue, 4-wide over h (float4 path); emits gated fp16 hi/lo
// ---------------------------------------------------------------------------
__global__ void conv_epilogue_kernel(const float* __restrict__ proj,
                                     const float* __restrict__ conv_state,
                                     const int* __restrict__ idx,
                                     const float* __restrict__ conv_w,
                                     __half2* __restrict__ ghi,
                                     __half2* __restrict__ glo,
                                     float* __restrict__ out_state) {
    int t = blockIdx.x * blockDim.x + threadIdx.x;
    if (t >= (B_SZ * H_SZ) / 4) return;
    int b = t >> 9;                 // / (H_SZ/4)
    int h = (t & 511) << 2;         // 4-aligned h
    int r = idx[b];

    const float4* cs =
        (const float4*)(conv_state + ((size_t)r * H_SZ + h) * 3);
    float4 ca = cs[0];
    float4 cb = cs[1];
    float4 cc = cs[2];

    const float* prow = proj + (size_t)b * 3 * H_SZ;
    float4 Bg = *(const float4*)(prow + h);
    float4 Cg = *(const float4*)(prow + H_SZ + h);
    float4 xx = *(const float4*)(prow + 2 * H_SZ + h);

    const float4* wv = (const float4*)(conv_w + h * 4);
    float4 w0 = wv[0], w1 = wv[1], w2 = wv[2], w3 = wv[3];

    float Bx0 = Bg.x * xx.x, Bx1 = Bg.y * xx.y;
    float Bx2 = Bg.z * xx.z, Bx3 = Bg.w * xx.w;

    float g0 = Cg.x * fmaf(ca.x, w0.x, fmaf(ca.y, w0.y, fmaf(ca.z, w0.z, Bx0 * w0.w)));
    float g1 = Cg.y * fmaf(ca.w, w1.x, fmaf(cb.x, w1.y, fmaf(cb.y, w1.z, Bx1 * w1.w)));
    float g2 = Cg.z * fmaf(cb.z, w2.x, fmaf(cb.w, w2.y, fmaf(cc.x, w2.z, Bx2 * w2.w)));
    float g3 = Cg.w * fmaf(cc.y, w3.x, fmaf(cc.z, w3.y, fmaf(cc.w, w3.z, Bx3 * w3.w)));

    __half h0 = __float2half_rn(g0), h1 = __float2half_rn(g1);
    __half h2 = __float2half_rn(g2), h3 = __float2half_rn(g3);
    ghi[2 * t]     = make_half2(h0, h1);
    ghi[2 * t + 1] = make_half2(h2, h3);
    glo[2 * t] = make_half2(__float2half_rn(g0 - __half2float(h0)),
                            __float2half_rn(g1 - __half2float(h1)));
    glo[2 * t + 1] = make_half2(__float2half_rn(g2 - __half2float(h2)),
                                __float2half_rn(g3 - __half2float(h3)));

    float4* os = (float4*)(out_state + ((size_t)r * H_SZ + h) * 3);
    os[0] = make_float4(ca.y, ca.z, Bx0, cb.x);
    os[1] = make_float4(cb.y, Bx1, cb.w, cc.x);
    os[2] = make_float4(Bx2, cc.z, cc.w, Bx3);
}

// ---------------------------------------------------------------------------
extern "C" void kernel_launch(void* const* d_in, const int* in_sizes, int n_in,
                              void* d_out, int out_size) {
    const float* hidden     = (const float*)d_in[0];
    const float* conv_state = (const float*)d_in[1];
    const int*   idx        = (const int*)d_in[2];
    const float* w_in       = (const float*)d_in[3];
    const float* w_out      = (const float*)d_in[4];
    const float* conv_w     = (const float*)d_in[5];

    float* y         = (float*)d_out;
    float* out_state = y + (size_t)B_SZ * H_SZ;

    void *proj, *hid_hi, *hid_lo, *win, *wout, *gat_hi, *gat_lo;
    cudaGetSymbolAddress(&proj, g_proj);
    cudaGetSymbolAddress(&hid_hi, g_hid_hi);
    cudaGetSymbolAddress(&hid_lo, g_hid_lo);
    cudaGetSymbolAddress(&win, g_win);
    cudaGetSymbolAddress(&wout, g_wout);
    cudaGetSymbolAddress(&gat_hi, g_gated_hi);
    cudaGetSymbolAddress(&gat_lo, g_gated_lo);

    cudaFuncSetAttribute(mma_gemm_kernel,
                         cudaFuncAttributeMaxDynamicSharedMemorySize,
                         SMEM_TOTAL);

    // Side stream + fork/join events (captured as graph dependencies).
    cudaStream_t side;
    cudaStreamCreateWithFlags(&side, cudaStreamNonBlocking);
    cudaEvent_t evFork, evJoin;
    cudaEventCreateWithFlags(&evFork, cudaEventDisableTiming);
    cudaEventCreateWithFlags(&evJoin, cudaEventDisableTiming);

    // fork: copy_state as a small co-resident grid (2 CTAs/SM), running
    // underneath prep + GEMM1 on the DRAM pipe (GEMM1 DRAM = 3%).
    cudaEventRecord(evFork, 0);
    cudaStreamWaitEvent(side, evFork, 0);
    copy_state_kernel<<<296, 256, 0, side>>>(
        (const float4*)conv_state, (float4*)out_state, (P_SZ * H_SZ * 3) / 4);
    cudaEventRecord(evJoin, side);

    // main stream: prep -> GEMM1
    prep_kernel<<<4096, 256>>>((const float4*)hidden, (const float4*)w_in,
                               (const float4*)w_out,
                               (__half2*)hid_hi, (__half2*)hid_lo,
                               (__half2*)win, (__half2*)wout);
    {
        int nTilesN = (3 * H_SZ) / 128;                 // 48
        int gemmCTAs = nTilesN * (B_SZ / 128);          // 768
        mma_gemm_kernel<<<gemmCTAs, 256, SMEM_TOTAL>>>(
            (const __half*)hid_hi, (const __half*)hid_lo, (const __half*)win,
            (float*)proj, 3 * H_SZ, nTilesN);
    }

    // join: epilogue overwrites scattered rows -> must follow the copy
    cudaStreamWaitEvent(0, evJoin, 0);
    conv_epilogue_kernel<<<(B_SZ * H_SZ / 4 + 255) / 256, 256>>>(
        (const float*)proj, conv_state, idx, conv_w,
        (__half2*)gat_hi, (__half2*)gat_lo, out_state);

    // GEMM2: y = gated @ w_out^T   [2048 x 2048]
    {
        int nTilesN = H_SZ / 128;                       // 16
        int gemmCTAs = nTilesN * (B_SZ / 128);          // 256
        mma_gemm_kernel<<<gemmCTAs, 256, SMEM_TOTAL>>>(
            (const __half*)gat_hi, (const __half*)gat_lo, (const __half*)wout,
            y, H_SZ, nTilesN);
    }
}

// round 17
// speedup vs baseline: 1.1950x; 1.0469x over previous
#include <cuda_runtime.h>
#include <cuda_fp16.h>
#include <cstdint>

#define B_SZ 2048
#define H_SZ 2048
#define P_SZ 8192
#define K_TOTAL 2048

// ---------------------------------------------------------------------------
// Scratch (__device__ globals; no cudaMalloc allowed)
// ---------------------------------------------------------------------------
__device__ __align__(1024) float g_proj[(size_t)B_SZ * 3 * H_SZ];
__device__ __align__(1024) __half g_hid_hi[(size_t)B_SZ * H_SZ];
__device__ __align__(1024) __half g_hid_lo[(size_t)B_SZ * H_SZ];
__device__ __align__(1024) __half g_win[(size_t)3 * H_SZ * H_SZ];
__device__ __align__(1024) __half g_wout[(size_t)H_SZ * H_SZ];
__device__ __align__(1024) __half g_gated_hi[(size_t)B_SZ * H_SZ];
__device__ __align__(1024) __half g_gated_lo[(size_t)B_SZ * H_SZ];

// ---------------------------------------------------------------------------
// Baseline-PTX helpers (legal on plain sm_103 target)
// ---------------------------------------------------------------------------
__device__ __forceinline__ uint32_t smem_u32(const void* p) {
    uint32_t a;
    asm("{ .reg .u64 t; cvta.to.shared.u64 t, %1; cvt.u32.u64 %0, t; }"
        : "=r"(a) : "l"(p));
    return a;
}

__device__ __forceinline__ void cp16(uint32_t dst, const void* src) {
    asm volatile("cp.async.cg.shared.global [%0], [%1], 16;"
                 :: "r"(dst), "l"(src));
}
#define CP_COMMIT() asm volatile("cp.async.commit_group;" ::: "memory")
#define CP_WAIT2()  asm volatile("cp.async.wait_group 2;" ::: "memory")

__device__ __forceinline__ void ldsm_x4(uint32_t* r, uint32_t addr) {
    asm volatile("ldmatrix.sync.aligned.m8n8.x4.shared.b16 {%0,%1,%2,%3}, [%4];"
                 : "=r"(r[0]), "=r"(r[1]), "=r"(r[2]), "=r"(r[3]) : "r"(addr));
}

__device__ __forceinline__ void mma_fp16(float* c, const uint32_t* a,
                                         const uint32_t* b) {
    asm volatile(
        "mma.sync.aligned.m16n8k16.row.col.f32.f16.f16.f32 "
        "{%0,%1,%2,%3}, {%4,%5,%6,%7}, {%8,%9}, {%0,%1,%2,%3};"
        : "+f"(c[0]), "+f"(c[1]), "+f"(c[2]), "+f"(c[3])
        : "r"(a[0]), "r"(a[1]), "r"(a[2]), "r"(a[3]), "r"(b[0]), "r"(b[1]));
}

// ---------------------------------------------------------------------------
// Split-fp16 2-product GEMM: D = Ah*B + Al*B (A = Ah+Al fp16; err ~2^-12).
// CTA tile 128M x 128N, BK=32, 4-stage cp.async (wait_group 2), ONE
// __syncthreads per iteration. 2 CTAs/SM -> 16 warps/SM.
// Stage: Ah@0(8K), Al@8K(8K), B@16K(8K) = 24KB; 4 stages = 96KB.
// Row = 64B, XOR swizzle off(r,c4)=r*64+((c4^((r>>1)&3))<<4).
// 8 warps: wm = wid&1 (64 M-rows each), wn = wid>>1 (32 N-cols each).
//
// TAIL COPY: when n4copy > 0, each CTA copies its grid-stride slice of
// conv_state AFTER its GEMM work. Wave-1/2 CTAs' copies (pure DRAM; GEMM
// DRAM = 3%) overlap wave-2/3 CTAs' MMA mainloops inside the same launch —
// deterministic intra-kernel overlap (stream-level concurrency proved
// ineffective in R14/R15). Only the last wave's slice is exposed (~14us).
// ---------------------------------------------------------------------------
#define BKI 32
#define NIT (K_TOTAL / BKI)          // 64
#define STG_BYTES 24576
#define NSTG 4
#define SMEM_TOTAL (NSTG * STG_BYTES)   // 96 KB
#define OFF_AL 8192
#define OFF_B  16384

__global__ __launch_bounds__(256, 2)
void mma_gemm_kernel(const __half* __restrict__ Ah,
                     const __half* __restrict__ Al,
                     const __half* __restrict__ Bm,
                     float* __restrict__ C, int Ntotal, int nTilesN,
                     const float4* __restrict__ csrc,
                     float4* __restrict__ cdst, int n4copy) {
    extern __shared__ __align__(1024) char smem[];
    const uint32_t sb = smem_u32(smem);
    const int tid = threadIdx.x;
    const int lane = tid & 31;
    const int wid = tid >> 5;
    const int wm = wid & 1;            // 2 warps along M (64 rows each)
    const int wn = wid >> 1;           // 4 warps along N (32 cols each)
    const int mBase = (blockIdx.x / nTilesN) * 128;
    const int nBase = (blockIdx.x % nTilesN) * 128;

    // ---- cp.async mapping: Ah/Al/B each 128 rows -> 2 reps; 6 cp16/thread ----
    const int ldRow = tid >> 2;        // 0..63
    const int ldC4 = tid & 3;
    const uint32_t sOff =
        (uint32_t)ldRow * 64 + ((((uint32_t)ldC4) ^ ((ldRow >> 1) & 3)) << 4);
    const size_t gRep = (size_t)64 * K_TOTAL;
    const __half* gAh = Ah + (size_t)(mBase + ldRow) * K_TOTAL + ldC4 * 8;
    const __half* gAl = Al + (size_t)(mBase + ldRow) * K_TOTAL + ldC4 * 8;
    const __half* gB  = Bm + (size_t)(nBase + ldRow) * K_TOTAL + ldC4 * 8;

#define ISSUE(sst, k0) do {                                                    \
        cp16((sst) + sOff,                    gAh + (k0));                      \
        cp16((sst) + sOff + 4096,             gAh + (k0) + gRep);               \
        cp16((sst) + OFF_AL + sOff,           gAl + (k0));                      \
        cp16((sst) + OFF_AL + sOff + 4096,    gAl + (k0) + gRep);               \
        cp16((sst) + OFF_B + sOff,            gB + (k0));                       \
        cp16((sst) + OFF_B + sOff + 4096,     gB + (k0) + gRep);                \
    } while (0)

    // ---- precomputed ldmatrix swizzle offsets (relative to stage base) ----
    uint32_t aOff[4][2];
    {
        const int rA = lane & 15;
        const uint32_t aK = (uint32_t)(lane >> 4);     // 0/1
#pragma unroll
        for (int i = 0; i < 4; i++) {
            int row = wm * 64 + i * 16 + rA;
            uint32_t base = (uint32_t)row * 64;
            uint32_t sw = (row >> 1) & 3;
#pragma unroll
            for (int kk = 0; kk < 2; kk++)
                aOff[i][kk] = base + (((aK + (uint32_t)(kk * 2)) ^ sw) << 4);
        }
    }
    uint32_t bOff[2][2];
    {
        const int rB = (lane & 7) + ((lane & 16) ? 8 : 0);
        const uint32_t bK = (uint32_t)((lane >> 3) & 1);
#pragma unroll
        for (int p = 0; p < 2; p++) {
            int row = wn * 32 + p * 16 + rB;
            uint32_t base = (uint32_t)row * 64;
            uint32_t sw = (row >> 1) & 3;
#pragma unroll
            for (int kk = 0; kk < 2; kk++)
                bOff[p][kk] = base + (((bK + (uint32_t)(kk * 2)) ^ sw) << 4);
        }
    }

    float acc[4][4][4];
#pragma unroll
    for (int i = 0; i < 4; i++)
#pragma unroll
        for (int j = 0; j < 4; j++)
#pragma unroll
            for (int v = 0; v < 4; v++) acc[i][j][v] = 0.f;

    // ---- pipeline prologue: 3 stages in flight ----
    ISSUE(sb + 0 * STG_BYTES, 0);
    CP_COMMIT();
    ISSUE(sb + 1 * STG_BYTES, BKI);
    CP_COMMIT();
    ISSUE(sb + 2 * STG_BYTES, 2 * BKI);
    CP_COMMIT();

    for (int it = 0; it < NIT; ++it) {
        CP_WAIT2();
        __syncthreads();

        if (it + 3 < NIT) {
            uint32_t sn = sb + (uint32_t)((it + 3) & 3) * STG_BYTES;
            ISSUE(sn, (it + 3) * BKI);
        }
        CP_COMMIT();

        const uint32_t sst = sb + (uint32_t)(it & 3) * STG_BYTES;
#pragma unroll
        for (int kk = 0; kk < 2; kk++) {           // two k16 halves of BK=32
            uint32_t af[16], bf[8];

            // Ah * B
#pragma unroll
            for (int i = 0; i < 4; i++)
                ldsm_x4(&af[i * 4], sst + aOff[i][kk]);
#pragma unroll
            for (int p = 0; p < 2; p++)
                ldsm_x4(&bf[p * 4], sst + OFF_B + bOff[p][kk]);
#pragma unroll
            for (int i = 0; i < 4; i++)
#pragma unroll
                for (int j = 0; j < 4; j++)
                    mma_fp16(acc[i][j], &af[i * 4],
                             &bf[(j >> 1) * 4 + (j & 1) * 2]);

            // Al * B (overwrite af; bf stays live)
#pragma unroll
            for (int i = 0; i < 4; i++)
                ldsm_x4(&af[i * 4], sst + OFF_AL + aOff[i][kk]);
#pragma unroll
            for (int i = 0; i < 4; i++)
#pragma unroll
                for (int j = 0; j < 4; j++)
                    mma_fp16(acc[i][j], &af[i * 4],
                             &bf[(j >> 1) * 4 + (j & 1) * 2]);
        }
    }

    // ---- epilogue: write C ----
    const int row0 = mBase + wm * 64 + (lane >> 2);
    const int col0 = nBase + wn * 32 + (lane & 3) * 2;
#pragma unroll
    for (int i = 0; i < 4; i++) {
#pragma unroll
        for (int j = 0; j < 4; j++) {
            float* p0 = C + (size_t)(row0 + i * 16) * Ntotal + col0 + j * 8;
            float* p1 = p0 + (size_t)8 * Ntotal;
            *(float2*)p0 = make_float2(acc[i][j][0], acc[i][j][1]);
            *(float2*)p1 = make_float2(acc[i][j][2], acc[i][j][3]);
        }
    }

    // ---- tail: per-CTA slice of the conv_state copy-through ----
    if (n4copy > 0) {
        int i = blockIdx.x * 256 + tid;
        int stride = gridDim.x * 256;
#pragma unroll 4
        for (; i < n4copy; i += stride) cdst[i] = csrc[i];
    }
#undef ISSUE
}

// ---------------------------------------------------------------------------
// Fused conversions (one launch, float4-vectorized)
// ---------------------------------------------------------------------------
#define N4_HID ((B_SZ * H_SZ) / 4)
#define N4_WIN ((3 * H_SZ * H_SZ) / 4)
#define N4_WOUT ((H_SZ * H_SZ) / 4)
#define N4_PREP (N4_HID + N4_WIN + N4_WOUT)

__global__ void prep_kernel(const float4* __restrict__ hidden,
                            const float4* __restrict__ w_in,
                            const float4* __restrict__ w_out,
                            __half2* __restrict__ hid_hi,
                            __half2* __restrict__ hid_lo,
                            __half2* __restrict__ win,
                            __half2* __restrict__ wout) {
    int i = blockIdx.x * blockDim.x + threadIdx.x;
    int stride = gridDim.x * blockDim.x;
    for (; i < N4_PREP; i += stride) {
        if (i < N4_HID) {
            float4 v = hidden[i];
            __half2 h0 = make_half2(__float2half_rn(v.x), __float2half_rn(v.y));
            __half2 h1 = make_half2(__float2half_rn(v.z), __float2half_rn(v.w));
            hid_hi[2 * i] = h0;
            hid_hi[2 * i + 1] = h1;
            hid_lo[2 * i] = make_half2(
                __float2half_rn(v.x - __half2float(__low2half(h0))),
                __float2half_rn(v.y - __half2float(__high2half(h0))));
            hid_lo[2 * i + 1] = make_half2(
                __float2half_rn(v.z - __half2float(__low2half(h1))),
                __float2half_rn(v.w - __half2float(__high2half(h1))));
        } else if (i < N4_HID + N4_WIN) {
            int j = i - N4_HID;
            float4 v = w_in[j];
            win[2 * j] = make_half2(__float2half_rn(v.x), __float2half_rn(v.y));
            win[2 * j + 1] = make_half2(__float2half_rn(v.z), __float2half_rn(v.w));
        } else {
            int j = i - N4_HID - N4_WIN;
            float4 v = w_out[j];
            wout[2 * j] = make_half2(__float2half_rn(v.x), __float2half_rn(v.y));
            wout[2 * j + 1] = make_half2(__float2half_rn(v.z), __float2half_rn(v.w));
        }
    }
}

// ---------------------------------------------------------------------------
// conv + gating epilogue, 4-wide over h (float4 path); emits gated fp16 hi/lo
// ---------------------------------------------------------------------------
__global__ void conv_epilogue_kernel(const float* __restrict__ proj,
                                     const float* __restrict__ conv_state,
                                     const int* __restrict__ idx,
                                     const float* __restrict__ conv_w,
                                     __half2* __restrict__ ghi,
                                     __half2* __restrict__ glo,
                                     float* __restrict__ out_state) {
    int t = blockIdx.x * blockDim.x + threadIdx.x;
    if (t >= (B_SZ * H_SZ) / 4) return;
    int b = t >> 9;                 // / (H_SZ/4)
    int h = (t & 511) << 2;         // 4-aligned h
    int r = idx[b];

    const float4* cs =
        (const float4*)(conv_state + ((size_t)r * H_SZ + h) * 3);
    float4 ca = cs[0];
    float4 cb = cs[1];
    float4 cc = cs[2];

    const float* prow = proj + (size_t)b * 3 * H_SZ;
    float4 Bg = *(const float4*)(prow + h);
    float4 Cg = *(const float4*)(prow + H_SZ + h);
    float4 xx = *(const float4*)(prow + 2 * H_SZ + h);

    const float4* wv = (const float4*)(conv_w + h * 4);
    float4 w0 = wv[0], w1 = wv[1], w2 = wv[2], w3 = wv[3];

    float Bx0 = Bg.x * xx.x, Bx1 = Bg.y * xx.y;
    float Bx2 = Bg.z * xx.z, Bx3 = Bg.w * xx.w;

    float g0 = Cg.x * fmaf(ca.x, w0.x, fmaf(ca.y, w0.y, fmaf(ca.z, w0.z, Bx0 * w0.w)));
    float g1 = Cg.y * fmaf(ca.w, w1.x, fmaf(cb.x, w1.y, fmaf(cb.y, w1.z, Bx1 * w1.w)));
    float g2 = Cg.z * fmaf(cb.z, w2.x, fmaf(cb.w, w2.y, fmaf(cc.x, w2.z, Bx2 * w2.w)));
    float g3 = Cg.w * fmaf(cc.y, w3.x, fmaf(cc.z, w3.y, fmaf(cc.w, w3.z, Bx3 * w3.w)));

    __half h0 = __float2half_rn(g0), h1 = __float2half_rn(g1);
    __half h2 = __float2half_rn(g2), h3 = __float2half_rn(g3);
    ghi[2 * t]     = make_half2(h0, h1);
    ghi[2 * t + 1] = make_half2(h2, h3);
    glo[2 * t] = make_half2(__float2half_rn(g0 - __half2float(h0)),
                            __float2half_rn(g1 - __half2float(h1)));
    glo[2 * t + 1] = make_half2(__float2half_rn(g2 - __half2float(h2)),
                                __float2half_rn(g3 - __half2float(h3)));

    float4* os = (float4*)(out_state + ((size_t)r * H_SZ + h) * 3);
    os[0] = make_float4(ca.y, ca.z, Bx0, cb.x);
    os[1] = make_float4(cb.y, Bx1, cb.w, cc.x);
    os[2] = make_float4(Bx2, cc.z, cc.w, Bx3);
}

// ---------------------------------------------------------------------------
extern "C" void kernel_launch(void* const* d_in, const int* in_sizes, int n_in,
                              void* d_out, int out_size) {
    const float* hidden     = (const float*)d_in[0];
    const float* conv_state = (const float*)d_in[1];
    const int*   idx        = (const int*)d_in[2];
    const float* w_in       = (const float*)d_in[3];
    const float* w_out      = (const float*)d_in[4];
    const float* conv_w     = (const float*)d_in[5];

    float* y         = (float*)d_out;
    float* out_state = y + (size_t)B_SZ * H_SZ;

    void *proj, *hid_hi, *hid_lo, *win, *wout, *gat_hi, *gat_lo;
    cudaGetSymbolAddress(&proj, g_proj);
    cudaGetSymbolAddress(&hid_hi, g_hid_hi);
    cudaGetSymbolAddress(&hid_lo, g_hid_lo);
    cudaGetSymbolAddress(&win, g_win);
    cudaGetSymbolAddress(&wout, g_wout);
    cudaGetSymbolAddress(&gat_hi, g_gated_hi);
    cudaGetSymbolAddress(&gat_lo, g_gated_lo);

    cudaFuncSetAttribute(mma_gemm_kernel,
                         cudaFuncAttributeMaxDynamicSharedMemorySize,
                         SMEM_TOTAL);

    // 1) fused fp16 conversions (hidden split + weight casts)
    prep_kernel<<<4096, 256>>>((const float4*)hidden, (const float4*)w_in,
                               (const float4*)w_out,
                               (__half2*)hid_hi, (__half2*)hid_lo,
                               (__half2*)win, (__half2*)wout);

    // 2) GEMM1 (proj = hidden @ w_in^T, [2048 x 6144]) with the conv_state
    //    copy as per-CTA tail work (intra-kernel wave overlap).
    {
        int nTilesN = (3 * H_SZ) / 128;                 // 48
        int gemmCTAs = nTilesN * (B_SZ / 128);          // 768
        int n4 = (P_SZ * H_SZ * 3) / 4;
        mma_gemm_kernel<<<gemmCTAs, 256, SMEM_TOTAL>>>(
            (const __half*)hid_hi, (const __half*)hid_lo, (const __half*)win,
            (float*)proj, 3 * H_SZ, nTilesN,
            (const float4*)conv_state, (float4*)out_state, n4);
    }

    // 3) conv + gate epilogue -> gated (fp16 hi/lo), scatter state rows
    //    (stream order guarantees the tail copy completed)
    conv_epilogue_kernel<<<(B_SZ * H_SZ / 4 + 255) / 256, 256>>>(
        (const float*)proj, conv_state, idx, conv_w,
        (__half2*)gat_hi, (__half2*)gat_lo, out_state);

    // 4) GEMM2: y = gated @ w_out^T   [2048 x 2048]
    {
        int nTilesN = H_SZ / 128;                       // 16
        int gemmCTAs = nTilesN * (B_SZ / 128);          // 256
        mma_gemm_kernel<<<gemmCTAs, 256, SMEM_TOTAL>>>(
            (const __half*)gat_hi, (const __half*)gat_lo, (const __half*)wout,
            y, H_SZ, nTilesN, nullptr, nullptr, 0);
    }
}